// round 5
// baseline (speedup 1.0000x reference)
#include <cuda_runtime.h>
#include <cstdint>

// ============================================================================
// LSTM cell via mma.sync tf32 (family-portable PTX).
// R5: 512 threads (16 warps = 4/SMSP) to hide latency and saturate the
// tensor pipe; 4-stage cp.async pipeline with ONE barrier per iteration.
//
// CTA tile: M=128, per-gate N=64 (N_eff=256), BK=32, K=2048 (64 iters).
// 16 warps = 4(M) x 4(gate); warp tile 32(M) x 64(one gate).
// ============================================================================

#define SA        36                         // A smem row stride (floats)
#define SBF       72                         // B smem per-gate row stride (floats)
#define A_BYTES   (128 * SA * 4)             // 18432
#define BG_BYTES  (32 * SBF * 4)             // 9216
#define STAGE_BYTES (A_BYTES + 4 * BG_BYTES) // 55296
#define NSTAGES   4
#define SMEM_BYTES (NSTAGES * STAGE_BYTES)   // 221184
#define SS        260                        // epilogue staging row stride (floats)

__device__ __forceinline__ uint32_t s2u(const void* p) {
    uint32_t a;
    asm("{ .reg .u64 t; cvta.to.shared.u64 t, %1; cvt.u32.u64 %0, t; }"
        : "=r"(a) : "l"(p));
    return a;
}
__device__ __forceinline__ void cp16(uint32_t dst, const float* src) {
    asm volatile("cp.async.cg.shared.global [%0], [%1], 16;" :: "r"(dst), "l"(src));
}
#define CP_COMMIT() asm volatile("cp.async.commit_group;" ::: "memory")
#define CP_WAIT(n)  asm volatile("cp.async.wait_group %0;" :: "n"(n) : "memory")

__device__ __forceinline__ void ldsm4(uint32_t* r, uint32_t addr) {
    asm volatile("ldmatrix.sync.aligned.m8n8.x4.shared.b16 {%0,%1,%2,%3}, [%4];"
                 : "=r"(r[0]), "=r"(r[1]), "=r"(r[2]), "=r"(r[3]) : "r"(addr));
}
__device__ __forceinline__ uint32_t f2tf(uint32_t bits) {
    float f = __uint_as_float(bits);
    uint32_t r;
    asm("cvt.rna.tf32.f32 %0, %1;" : "=r"(r) : "f"(f));
    return r;
}
__device__ __forceinline__ void mma8(float* d, const uint32_t* a, const uint32_t* b) {
    asm volatile(
        "mma.sync.aligned.m16n8k8.row.col.f32.tf32.tf32.f32 "
        "{%0,%1,%2,%3}, {%4,%5,%6,%7}, {%8,%9}, {%0,%1,%2,%3};"
        : "+f"(d[0]), "+f"(d[1]), "+f"(d[2]), "+f"(d[3])
        : "r"(a[0]), "r"(a[1]), "r"(a[2]), "r"(a[3]), "r"(b[0]), "r"(b[1]));
}

__device__ __forceinline__ float sigf(float v) {
    return __fdividef(1.0f, 1.0f + __expf(-v));
}
__device__ __forceinline__ float tanhf_e(float v) {
    float ax = fabsf(v);
    float e = __expf(-2.0f * ax);
    float t = __fdividef(1.0f - e, 1.0f + e);
    return copysignf(t, v);
}

__device__ __forceinline__ void load_stage(
    int T, uint32_t sb, int tid, int m0, int n0,
    const float* __restrict__ x, const float* __restrict__ h,
    const float* __restrict__ Wf, const float* __restrict__ Wi,
    const float* __restrict__ Wc, const float* __restrict__ Wo)
{
    const int s = T & (NSTAGES - 1);
    const uint32_t Ab = sb + s * STAGE_BYTES;
    const int k0 = T * 32;
    const float* Asrc = (k0 < 1024) ? x : h;
    const int kc = (k0 < 1024) ? k0 : k0 - 1024;

    // A tile: 128 rows x 32 floats = 1024 x 16B chunks (2/thread)
    #pragma unroll
    for (int c = 0; c < 2; c++) {
        int ci = c * 512 + tid;
        int row = ci >> 3, col = ci & 7;
        cp16(Ab + row * (SA * 4) + col * 16,
             Asrc + (size_t)(m0 + row) * 1024 + kc + col * 4);
    }
    // B tiles: 4 gates x 32 k-rows x 64 floats = 2048 x 16B chunks (4/thread);
    // gate g == chunk index c (each c covers exactly 512 chunks).
    const uint32_t Bb = Ab + A_BYTES;
    #pragma unroll
    for (int c = 0; c < 4; c++) {
        int rem = tid;                 // ci & 511 with ci = c*512 + tid
        int kr = rem >> 4, col = rem & 15;
        const float* Wg = (c == 0) ? Wf : (c == 1) ? Wi : (c == 2) ? Wc : Wo;
        cp16(Bb + c * BG_BYTES + kr * (SBF * 4) + col * 16,
             Wg + (size_t)(k0 + kr) * 1024 + n0 + col * 4);
    }
}

__global__ void __launch_bounds__(512, 1)
lstm_mma(const float* __restrict__ x, const float* __restrict__ h,
         const float* __restrict__ cellp,
         const float* __restrict__ Wf, const float* __restrict__ bf,
         const float* __restrict__ Wi, const float* __restrict__ bi,
         const float* __restrict__ Wc, const float* __restrict__ bc,
         const float* __restrict__ Wo, const float* __restrict__ bo,
         float* __restrict__ outh, float* __restrict__ outc)
{
    extern __shared__ float sm[];
    const uint32_t sb = s2u(sm);

    const int tid  = threadIdx.x;
    const int lane = tid & 31;
    const int wid  = tid >> 5;
    const int g    = wid & 3;             // gate handled by this warp
    const int wmi  = wid >> 2;            // M quarter (0..3)
    const int m0   = blockIdx.x * 128;
    const int n0   = blockIdx.y * 64;

    // ldmatrix lane address pieces (A frags, tf32-as-b16 trick)
    const int lr    = lane & 7;
    const int sel   = lane >> 3;
    const int arow  = (sel & 1) * 8 + lr;     // row within m16 tile
    const int acolB = (sel >> 1) * 16;        // byte offset within k8
    // B frag lane pieces (conflict-free: bank = 8*kq + nq)
    const int kq = lane & 3;
    const int nq = lane >> 2;

    float acc[2][8][4];
    #pragma unroll
    for (int mt = 0; mt < 2; mt++)
        #pragma unroll
        for (int nt = 0; nt < 8; nt++)
            #pragma unroll
            for (int j = 0; j < 4; j++) acc[mt][nt][j] = 0.0f;

    load_stage(0, sb, tid, m0, n0, x, h, Wf, Wi, Wc, Wo); CP_COMMIT();
    load_stage(1, sb, tid, m0, n0, x, h, Wf, Wi, Wc, Wo); CP_COMMIT();

    for (int t = 0; t < 64; t++) {
        if (t < 62) {
            load_stage(t + 2, sb, tid, m0, n0, x, h, Wf, Wi, Wc, Wo);
            CP_COMMIT();
            CP_WAIT(2);
        } else if (t == 62) {
            CP_WAIT(1);
        } else {
            CP_WAIT(0);
        }
        __syncthreads();   // single barrier per iter (4 stages, skew <= 1 iter safe)

        const uint32_t Ab = sb + (t & (NSTAGES - 1)) * STAGE_BYTES;
        const uint32_t Bg = Ab + A_BYTES + g * BG_BYTES;

        #pragma unroll
        for (int ks = 0; ks < 4; ks++) {
            uint32_t a[2][4];
            #pragma unroll
            for (int mt = 0; mt < 2; mt++) {
                uint32_t ad = Ab + (uint32_t)(wmi * 32 + mt * 16 + arow) * (SA * 4)
                                 + (uint32_t)(ks * 32 + acolB);
                ldsm4(a[mt], ad);
            }
            uint32_t b[8][2];
            #pragma unroll
            for (int nt = 0; nt < 8; nt++) {
                uint32_t bd = Bg + (uint32_t)(ks * 8 + kq) * (SBF * 4)
                                 + (uint32_t)(nt * 8 + nq) * 4;
                asm volatile("ld.shared.b32 %0, [%1];" : "=r"(b[nt][0]) : "r"(bd));
                asm volatile("ld.shared.b32 %0, [%1];" : "=r"(b[nt][1]) : "r"(bd + 4 * SBF * 4));
            }
            #pragma unroll
            for (int mt = 0; mt < 2; mt++)
                #pragma unroll
                for (int j = 0; j < 4; j++) a[mt][j] = f2tf(a[mt][j]);
            #pragma unroll
            for (int nt = 0; nt < 8; nt++) {
                b[nt][0] = f2tf(b[nt][0]);
                b[nt][1] = f2tf(b[nt][1]);
            }
            #pragma unroll
            for (int mt = 0; mt < 2; mt++)
                #pragma unroll
                for (int nt = 0; nt < 8; nt++)
                    mma8(acc[mt][nt], a[mt], b[nt]);
        }
    }
    __syncthreads();       // protect smem reuse for staging

    // ---- stage gate values through smem (gates live in different warps) ----
    #pragma unroll
    for (int mt = 0; mt < 2; mt++) {
        #pragma unroll
        for (int nt = 0; nt < 8; nt++) {
            int r0 = wmi * 32 + mt * 16 + (lane >> 2);
            int cb = g * 64 + nt * 8 + (lane & 3) * 2;
            *(float2*)&sm[(size_t)r0 * SS + cb]       = make_float2(acc[mt][nt][0], acc[mt][nt][1]);
            *(float2*)&sm[(size_t)(r0 + 8) * SS + cb] = make_float2(acc[mt][nt][2], acc[mt][nt][3]);
        }
    }
    __syncthreads();

    // ---- fused LSTM combine + store ----
    const int nl   = tid & 63;
    const int mseg = tid >> 6;            // 0..7
    const int n    = n0 + nl;
    const float Bf = __ldg(bf + n);
    const float Bi = __ldg(bi + n);
    const float Bc = __ldg(bc + n);
    const float Bo = __ldg(bo + n);

    #pragma unroll 4
    for (int r = 0; r < 16; r++) {
        int m = r * 8 + mseg;
        const float* row = &sm[(size_t)m * SS];
        float gf = row[nl]       + Bf;
        float gi = row[64 + nl]  + Bi;
        float gc = row[128 + nl] + Bc;
        float go = row[192 + nl] + Bo;

        float F  = sigf(gf);
        float I  = sigf(gi);
        float O  = sigf(go);
        float CD = tanhf_e(gc);

        size_t gidx = (size_t)(m0 + m) * 1024 + n;
        float cold = __ldg(cellp + gidx);
        float nc = fmaf(F, cold, I * CD);
        float nh = O * tanhf_e(nc);
        outh[gidx] = nh;
        outc[gidx] = nc;
    }
}

extern "C" void kernel_launch(void* const* d_in, const int* in_sizes, int n_in,
                              void* d_out, int out_size)
{
    const float* x    = (const float*)d_in[0];   // [B, 1024]
    const float* h    = (const float*)d_in[1];   // [B, 1024]
    const float* cell = (const float*)d_in[2];   // [B, 1024]
    const float* Wf   = (const float*)d_in[3];   // [2048, 1024]
    const float* bf   = (const float*)d_in[4];
    const float* Wi   = (const float*)d_in[5];
    const float* bi   = (const float*)d_in[6];
    const float* Wc   = (const float*)d_in[7];
    const float* bc   = (const float*)d_in[8];
    const float* Wo   = (const float*)d_in[9];
    const float* bo   = (const float*)d_in[10];

    const int B = in_sizes[0] / 1024;            // 8192

    static bool attr_set = false;
    if (!attr_set) {
        cudaFuncSetAttribute(lstm_mma, cudaFuncAttributeMaxDynamicSharedMemorySize,
                             SMEM_BYTES);
        attr_set = true;
    }

    float* outh = (float*)d_out;
    float* outc = (float*)d_out + (size_t)B * 1024;

    dim3 grid(B / 128, 16);
    lstm_mma<<<grid, 512, SMEM_BYTES>>>(x, h, cell, Wf, bf, Wi, bi, Wc, bc,
                                        Wo, bo, outh, outc);
}

// round 6
// speedup vs baseline: 1.2424x; 1.2424x over previous
#include <cuda_runtime.h>
#include <cuda_fp16.h>
#include <cstdint>

// ============================================================================
// LSTM cell via mma.sync fp16 m16n8k16 (f32 accumulate).
// fp16 mantissa (11 bits) == tf32 mantissa, but HALF the HMMA instructions.
// Inputs converted fp32->fp16 once at tile load; mainloop is pure
// ldmatrix + HMMA (no CVT, no scalar LDS).
//
// CTA tile: M=128, per-gate N=64 (4 gates), BK=32, K=2048 (64 iters).
// 8 warps = 2(M) x 4(gate); warp tile 64 x 64. 3 smem stages, register-staged
// global loads (no cp.async), one __syncthreads per iter.
// ============================================================================

#define SA_B      80                          // A smem row stride bytes (32 fp16 + pad)
#define SB_B      144                         // B smem row stride bytes (64 fp16 + pad)
#define A_BYTES   (128 * SA_B)                // 10240
#define BG_BYTES  (32 * SB_B)                 // 4608 per gate
#define STAGE_BYTES (A_BYTES + 4 * BG_BYTES)  // 28672
#define NSTAGES   3
#define MAIN_BYTES (NSTAGES * STAGE_BYTES)    // 86016
#define SS        260                         // epilogue staging stride (floats)
#define EPI_BYTES (128 * SS * 4)              // 133120
#define SMEM_BYTES EPI_BYTES                  // max(MAIN_BYTES, EPI_BYTES)

__device__ __forceinline__ uint32_t s2u(const void* p) {
    uint32_t a;
    asm("{ .reg .u64 t; cvta.to.shared.u64 t, %1; cvt.u32.u64 %0, t; }"
        : "=r"(a) : "l"(p));
    return a;
}
__device__ __forceinline__ void ldsm4(uint32_t* r, uint32_t addr) {
    asm volatile("ldmatrix.sync.aligned.m8n8.x4.shared.b16 {%0,%1,%2,%3}, [%4];"
                 : "=r"(r[0]), "=r"(r[1]), "=r"(r[2]), "=r"(r[3]) : "r"(addr));
}
__device__ __forceinline__ void ldsm4t(uint32_t* r, uint32_t addr) {
    asm volatile("ldmatrix.sync.aligned.m8n8.x4.trans.shared.b16 {%0,%1,%2,%3}, [%4];"
                 : "=r"(r[0]), "=r"(r[1]), "=r"(r[2]), "=r"(r[3]) : "r"(addr));
}
__device__ __forceinline__ void mma16(float* d, const uint32_t* a, const uint32_t* b) {
    asm volatile(
        "mma.sync.aligned.m16n8k16.row.col.f32.f16.f16.f32 "
        "{%0,%1,%2,%3}, {%4,%5,%6,%7}, {%8,%9}, {%0,%1,%2,%3};"
        : "+f"(d[0]), "+f"(d[1]), "+f"(d[2]), "+f"(d[3])
        : "r"(a[0]), "r"(a[1]), "r"(a[2]), "r"(a[3]), "r"(b[0]), "r"(b[1]));
}
__device__ __forceinline__ void sts64(uint32_t addr, uint32_t u0, uint32_t u1) {
    asm volatile("st.shared.v2.b32 [%0], {%1, %2};" :: "r"(addr), "r"(u0), "r"(u1));
}
__device__ __forceinline__ uint32_t pack2(float lo, float hi) {
    __half2 h = __floats2half2_rn(lo, hi);
    return *reinterpret_cast<uint32_t*>(&h);
}

__device__ __forceinline__ float sigf(float v) {
    return __fdividef(1.0f, 1.0f + __expf(-v));
}
__device__ __forceinline__ float tanhf_e(float v) {
    float ax = fabsf(v);
    float e = __expf(-2.0f * ax);
    float t = __fdividef(1.0f - e, 1.0f + e);
    return copysignf(t, v);
}

struct GRegs { float4 a[4]; float4 b[8]; };

// Issue global loads for stage T into registers.
__device__ __forceinline__ void ldg_stage(
    int T, int tid, int m0, int n0, GRegs& G,
    const float* __restrict__ x, const float* __restrict__ h,
    const float* __restrict__ Wf, const float* __restrict__ Wi,
    const float* __restrict__ Wc, const float* __restrict__ Wo)
{
    const int k0 = T * 32;
    const float* Asrc = (k0 < 1024) ? x : h;
    const int kc = (k0 < 1024) ? k0 : k0 - 1024;

    // A: 128 rows x 32 k f32 = 1024 float4 (4/thread)
    #pragma unroll
    for (int c = 0; c < 4; c++) {
        int idx = c * 256 + tid;
        int row = idx >> 3, k4 = (idx & 7) * 4;
        G.a[c] = *reinterpret_cast<const float4*>(
            Asrc + (size_t)(m0 + row) * 1024 + kc + k4);
    }
    // B: 4 gates x 32 k x 64 n f32 = 2048 float4 (8/thread); gate = c>>1
    #pragma unroll
    for (int c = 0; c < 8; c++) {
        int rem = (c & 1) * 256 + tid;           // 0..511 within gate
        int kr = rem >> 4, n4 = (rem & 15) * 4;
        const float* Wg = ((c >> 1) == 0) ? Wf : ((c >> 1) == 1) ? Wi
                        : ((c >> 1) == 2) ? Wc : Wo;
        G.b[c] = *reinterpret_cast<const float4*>(
            Wg + (size_t)(k0 + kr) * 1024 + n0 + n4);
    }
}

// Convert + store stage T's registers into smem stage (T % NSTAGES).
__device__ __forceinline__ void sts_stage(int T, int tid, uint32_t sb, const GRegs& G)
{
    const uint32_t Ab = sb + (T % NSTAGES) * STAGE_BYTES;
    #pragma unroll
    for (int c = 0; c < 4; c++) {
        int idx = c * 256 + tid;
        int row = idx >> 3, k4 = (idx & 7) * 4;
        sts64(Ab + row * SA_B + k4 * 2,
              pack2(G.a[c].x, G.a[c].y), pack2(G.a[c].z, G.a[c].w));
    }
    const uint32_t Bb = Ab + A_BYTES;
    #pragma unroll
    for (int c = 0; c < 8; c++) {
        int rem = (c & 1) * 256 + tid;
        int kr = rem >> 4, n4 = (rem & 15) * 4;
        sts64(Bb + (c >> 1) * BG_BYTES + kr * SB_B + n4 * 2,
              pack2(G.b[c].x, G.b[c].y), pack2(G.b[c].z, G.b[c].w));
    }
}

__global__ void __launch_bounds__(256, 1)
lstm_mma(const float* __restrict__ x, const float* __restrict__ h,
         const float* __restrict__ cellp,
         const float* __restrict__ Wf, const float* __restrict__ bf,
         const float* __restrict__ Wi, const float* __restrict__ bi,
         const float* __restrict__ Wc, const float* __restrict__ bc,
         const float* __restrict__ Wo, const float* __restrict__ bo,
         float* __restrict__ outh, float* __restrict__ outc)
{
    extern __shared__ float sm[];
    const uint32_t sb = s2u(sm);

    const int tid  = threadIdx.x;
    const int lane = tid & 31;
    const int wid  = tid >> 5;
    const int g    = wid & 3;             // gate handled by this warp
    const int wm   = wid >> 2;            // M half (0/1)
    const int m0   = blockIdx.x * 128;
    const int n0   = blockIdx.y * 64;

    // ldmatrix lane address pieces
    const int l15  = lane & 15;
    const int ahi  = (lane >> 4) * 16;    // A: 16B column select (k0-7 / k8-15)
    const int bhi  = (lane >> 4) * 8;     // B: n-chunk select (n0-7 / n8-15)

    float acc[4][8][4];
    #pragma unroll
    for (int mt = 0; mt < 4; mt++)
        #pragma unroll
        for (int nt = 0; nt < 8; nt++)
            #pragma unroll
            for (int j = 0; j < 4; j++) acc[mt][nt][j] = 0.0f;

    GRegs G;
    ldg_stage(0, tid, m0, n0, G, x, h, Wf, Wi, Wc, Wo);
    sts_stage(0, tid, sb, G);
    ldg_stage(1, tid, m0, n0, G, x, h, Wf, Wi, Wc, Wo);

    for (int t = 0; t < 64; t++) {
        if (t + 1 < 64) sts_stage(t + 1, tid, sb, G);
        if (t + 2 < 64) ldg_stage(t + 2, tid, m0, n0, G, x, h, Wf, Wi, Wc, Wo);
        __syncthreads();

        const uint32_t Ab = sb + (t % NSTAGES) * STAGE_BYTES;
        const uint32_t Bg = Ab + A_BYTES + g * BG_BYTES;

        #pragma unroll
        for (int ks = 0; ks < 2; ks++) {          // two k16 steps
            uint32_t a[4][4];
            #pragma unroll
            for (int mt = 0; mt < 4; mt++) {
                uint32_t ad = Ab + (uint32_t)(wm * 64 + mt * 16 + l15) * SA_B
                                 + (uint32_t)(ks * 32 + ahi);
                ldsm4(a[mt], ad);
            }
            uint32_t b[8][2];
            #pragma unroll
            for (int np = 0; np < 4; np++) {      // n16 pairs
                uint32_t r[4];
                uint32_t bd = Bg + (uint32_t)(ks * 16 + l15) * SB_B
                                 + (uint32_t)(np * 16 + bhi) * 2;
                ldsm4t(r, bd);
                b[np * 2][0]     = r[0]; b[np * 2][1]     = r[1];
                b[np * 2 + 1][0] = r[2]; b[np * 2 + 1][1] = r[3];
            }
            #pragma unroll
            for (int mt = 0; mt < 4; mt++)
                #pragma unroll
                for (int nt = 0; nt < 8; nt++)
                    mma16(acc[mt][nt], a[mt], b[nt]);
        }
    }
    __syncthreads();       // mainloop done; smem reused for staging

    // ---- stage gate values through smem (gates live in different warps) ----
    #pragma unroll
    for (int mt = 0; mt < 4; mt++) {
        #pragma unroll
        for (int nt = 0; nt < 8; nt++) {
            int r0 = wm * 64 + mt * 16 + (lane >> 2);
            int cb = g * 64 + nt * 8 + (lane & 3) * 2;
            *(float2*)&sm[(size_t)r0 * SS + cb]       = make_float2(acc[mt][nt][0], acc[mt][nt][1]);
            *(float2*)&sm[(size_t)(r0 + 8) * SS + cb] = make_float2(acc[mt][nt][2], acc[mt][nt][3]);
        }
    }
    __syncthreads();

    // ---- fused LSTM combine + store ----
    const int nl   = tid & 63;
    const int mseg = tid >> 6;            // 0..3
    const int n    = n0 + nl;
    const float Bf = __ldg(bf + n);
    const float Bi = __ldg(bi + n);
    const float Bc = __ldg(bc + n);
    const float Bo = __ldg(bo + n);

    #pragma unroll 4
    for (int r = 0; r < 32; r++) {
        int m = r * 4 + mseg;
        const float* row = &sm[(size_t)m * SS];
        float gf = row[nl]       + Bf;
        float gi = row[64 + nl]  + Bi;
        float gc = row[128 + nl] + Bc;
        float go = row[192 + nl] + Bo;

        float F  = sigf(gf);
        float I  = sigf(gi);
        float O  = sigf(go);
        float CD = tanhf_e(gc);

        size_t gidx = (size_t)(m0 + m) * 1024 + n;
        float cold = __ldg(cellp + gidx);
        float nc = fmaf(F, cold, I * CD);
        float nh = O * tanhf_e(nc);
        outh[gidx] = nh;
        outc[gidx] = nc;
    }
}

extern "C" void kernel_launch(void* const* d_in, const int* in_sizes, int n_in,
                              void* d_out, int out_size)
{
    const float* x    = (const float*)d_in[0];   // [B, 1024]
    const float* h    = (const float*)d_in[1];   // [B, 1024]
    const float* cell = (const float*)d_in[2];   // [B, 1024]
    const float* Wf   = (const float*)d_in[3];   // [2048, 1024]
    const float* bf   = (const float*)d_in[4];
    const float* Wi   = (const float*)d_in[5];
    const float* bi   = (const float*)d_in[6];
    const float* Wc   = (const float*)d_in[7];
    const float* bc   = (const float*)d_in[8];
    const float* Wo   = (const float*)d_in[9];
    const float* bo   = (const float*)d_in[10];

    const int B = in_sizes[0] / 1024;            // 8192

    static bool attr_set = false;
    if (!attr_set) {
        cudaFuncSetAttribute(lstm_mma, cudaFuncAttributeMaxDynamicSharedMemorySize,
                             SMEM_BYTES);
        attr_set = true;
    }

    float* outh = (float*)d_out;
    float* outc = (float*)d_out + (size_t)B * 1024;

    dim3 grid(B / 128, 16);
    lstm_mma<<<grid, 256, SMEM_BYTES>>>(x, h, cell, Wf, bf, Wi, bi, Wc, bc,
                                        Wo, bo, outh, outc);
}

// round 8
// speedup vs baseline: 1.3996x; 1.1265x over previous
#include <cuda_runtime.h>
#include <cuda_fp16.h>
#include <cstdint>

// ============================================================================
// LSTM cell, two kernels:
//  1) convert: fp32 -> fp16 into __device__ globals (combined [x|h], W per gate)
//  2) GEMM via mma.sync fp16 m16n8k16, pure cp.async mainloop (no CVT/staging),
//     BK=64, fragment double-buffering, fused LSTM epilogue.
// CTA: M=128, per-gate N=64 (4 gates), 8 warps = 2(M) x 4(gate), warp 64x64.
// R8 fix: NSTAGES=4 (prefetch distance 2 raced with readers at 3 stages).
// ============================================================================

#define BATCH     8192
#define SA_B      144                         // A smem row stride bytes (64 fp16 + 16 pad)
#define SB_B      144                         // B smem row stride bytes
#define A_BYTES   (128 * SA_B)                // 18432
#define BG_BYTES  (64 * SB_B)                 // 9216 per gate
#define STAGE_BYTES (A_BYTES + 4 * BG_BYTES)  // 55296
#define NSTAGES   4
#define SS        260                         // epilogue staging stride (floats)
#define SMEM_BYTES (NSTAGES * STAGE_BYTES)    // 221184 (> epi 133120)

__device__ static __half A_h[(size_t)BATCH * 2048];      // combined [x|h], 32MB
__device__ static __half W_h[4][(size_t)2048 * 1024];    // per-gate weights, 16MB

// ---------------------------------------------------------------- convert ---
__global__ void __launch_bounds__(256) convert_kernel(
    const float* __restrict__ x, const float* __restrict__ h,
    const float* __restrict__ Wf, const float* __restrict__ Wi,
    const float* __restrict__ Wc, const float* __restrict__ Wo)
{
    const size_t NA = (size_t)BATCH * 2048 / 4;    // float4 count for A
    const size_t NW = (size_t)2048 * 1024 / 4;     // per gate
    const size_t total = NA + 4 * NW;
    const size_t stride = (size_t)gridDim.x * blockDim.x;

    for (size_t i = (size_t)blockIdx.x * blockDim.x + threadIdx.x;
         i < total; i += stride) {
        float4 v;
        __half* dst;
        if (i < NA) {
            size_t m = i >> 9;              // 512 float4 per 2048-row
            size_t kq = i & 511;
            size_t k = kq * 4;
            const float* src = (k < 1024) ? (x + m * 1024 + k)
                                          : (h + m * 1024 + (k - 1024));
            v = *reinterpret_cast<const float4*>(src);
            dst = &A_h[i * 4];
        } else {
            size_t j = i - NA;
            size_t g = j / NW;
            size_t r = j - g * NW;
            const float* Wg = (g == 0) ? Wf : (g == 1) ? Wi : (g == 2) ? Wc : Wo;
            v = *reinterpret_cast<const float4*>(Wg + r * 4);
            dst = &W_h[g][r * 4];
        }
        __half2 lo = __floats2half2_rn(v.x, v.y);
        __half2 hi = __floats2half2_rn(v.z, v.w);
        uint2 out = { *reinterpret_cast<uint32_t*>(&lo), *reinterpret_cast<uint32_t*>(&hi) };
        *reinterpret_cast<uint2*>(dst) = out;
    }
}

// ------------------------------------------------------------------ GEMM ----
__device__ __forceinline__ uint32_t s2u(const void* p) {
    uint32_t a;
    asm("{ .reg .u64 t; cvta.to.shared.u64 t, %1; cvt.u32.u64 %0, t; }"
        : "=r"(a) : "l"(p));
    return a;
}
__device__ __forceinline__ void cp16(uint32_t dst, const __half* src) {
    asm volatile("cp.async.cg.shared.global [%0], [%1], 16;" :: "r"(dst), "l"(src));
}
#define CP_COMMIT() asm volatile("cp.async.commit_group;" ::: "memory")
#define CP_WAIT(n)  asm volatile("cp.async.wait_group %0;" :: "n"(n) : "memory")

__device__ __forceinline__ void ldsm4(uint32_t* r, uint32_t addr) {
    asm volatile("ldmatrix.sync.aligned.m8n8.x4.shared.b16 {%0,%1,%2,%3}, [%4];"
                 : "=r"(r[0]), "=r"(r[1]), "=r"(r[2]), "=r"(r[3]) : "r"(addr));
}
__device__ __forceinline__ void ldsm4t(uint32_t* r, uint32_t addr) {
    asm volatile("ldmatrix.sync.aligned.m8n8.x4.trans.shared.b16 {%0,%1,%2,%3}, [%4];"
                 : "=r"(r[0]), "=r"(r[1]), "=r"(r[2]), "=r"(r[3]) : "r"(addr));
}
__device__ __forceinline__ void mma16(float* d, const uint32_t* a, const uint32_t* b) {
    asm volatile(
        "mma.sync.aligned.m16n8k16.row.col.f32.f16.f16.f32 "
        "{%0,%1,%2,%3}, {%4,%5,%6,%7}, {%8,%9}, {%0,%1,%2,%3};"
        : "+f"(d[0]), "+f"(d[1]), "+f"(d[2]), "+f"(d[3])
        : "r"(a[0]), "r"(a[1]), "r"(a[2]), "r"(a[3]), "r"(b[0]), "r"(b[1]));
}
__device__ __forceinline__ float sigf(float v) {
    return __fdividef(1.0f, 1.0f + __expf(-v));
}
__device__ __forceinline__ float tanhf_e(float v) {
    float ax = fabsf(v);
    float e = __expf(-2.0f * ax);
    float t = __fdividef(1.0f - e, 1.0f + e);
    return copysignf(t, v);
}

// cp.async one BK=64 stage: A 1024 chunks (4/thread), B 2048 chunks (8/thread)
__device__ __forceinline__ void load_stage(int T, int tid, uint32_t sb, int m0, int n0)
{
    const uint32_t Ab = sb + (T % NSTAGES) * STAGE_BYTES;
    const int k0 = T * 64;
    #pragma unroll
    for (int c = 0; c < 4; c++) {
        int idx = c * 256 + tid;
        int row = idx >> 3, col = idx & 7;
        cp16(Ab + row * SA_B + col * 16,
             &A_h[(size_t)(m0 + row) * 2048 + k0 + col * 8]);
    }
    const uint32_t Bb = Ab + A_BYTES;
    #pragma unroll
    for (int c = 0; c < 8; c++) {
        int idx = c * 256 + tid;
        int g = idx >> 9;                // constant per unrolled c
        int rem = idx & 511;
        int kr = rem >> 3, col = rem & 7;
        cp16(Bb + g * BG_BYTES + kr * SB_B + col * 16,
             &W_h[g][(size_t)(k0 + kr) * 1024 + n0 + col * 8]);
    }
}

__global__ void __launch_bounds__(256, 1)
lstm_mma(const float* __restrict__ cellp,
         const float* __restrict__ bf, const float* __restrict__ bi,
         const float* __restrict__ bc, const float* __restrict__ bo,
         float* __restrict__ outh, float* __restrict__ outc)
{
    extern __shared__ float sm[];
    const uint32_t sb = s2u(sm);

    const int tid  = threadIdx.x;
    const int lane = tid & 31;
    const int wid  = tid >> 5;
    const int g    = wid & 3;             // gate handled by this warp
    const int wm   = wid >> 2;            // M half (0/1)
    const int m0   = blockIdx.x * 128;
    const int n0   = blockIdx.y * 64;

    const int l15  = lane & 15;
    const int ahi  = (lane >> 4) * 16;    // A: 16B k-half select
    const int bhi  = (lane >> 4) * 8;     // B: n-chunk select

    float acc[4][8][4];
    #pragma unroll
    for (int mt = 0; mt < 4; mt++)
        #pragma unroll
        for (int nt = 0; nt < 8; nt++)
            #pragma unroll
            for (int j = 0; j < 4; j++) acc[mt][nt][j] = 0.0f;

    load_stage(0, tid, sb, m0, n0); CP_COMMIT();
    load_stage(1, tid, sb, m0, n0); CP_COMMIT();

    for (int t = 0; t < 32; t++) {
        if (t < 30) {
            load_stage(t + 2, tid, sb, m0, n0);
            CP_COMMIT();
            CP_WAIT(2);
        } else if (t == 30) {
            CP_WAIT(1);
        } else {
            CP_WAIT(0);
        }
        __syncthreads();

        const uint32_t Ab = sb + (t % NSTAGES) * STAGE_BYTES;
        const uint32_t Bg = Ab + A_BYTES + g * BG_BYTES;

        uint32_t afr[2][4][4], bfr[2][8][2];

        // prologue: frags for ks=0
        #pragma unroll
        for (int mt = 0; mt < 4; mt++)
            ldsm4(afr[0][mt], Ab + (uint32_t)(wm * 64 + mt * 16 + l15) * SA_B + ahi);
        #pragma unroll
        for (int np = 0; np < 4; np++) {
            uint32_t r[4];
            ldsm4t(r, Bg + (uint32_t)l15 * SB_B + (uint32_t)(np * 16 + bhi) * 2);
            bfr[0][np * 2][0] = r[0]; bfr[0][np * 2][1] = r[1];
            bfr[0][np * 2 + 1][0] = r[2]; bfr[0][np * 2 + 1][1] = r[3];
        }

        #pragma unroll
        for (int ks = 0; ks < 4; ks++) {          // four k16 steps (BK=64)
            const int cur = ks & 1, nxt = cur ^ 1;
            if (ks < 3) {
                #pragma unroll
                for (int mt = 0; mt < 4; mt++)
                    ldsm4(afr[nxt][mt],
                          Ab + (uint32_t)(wm * 64 + mt * 16 + l15) * SA_B
                             + (uint32_t)((ks + 1) * 32 + ahi));
                #pragma unroll
                for (int np = 0; np < 4; np++) {
                    uint32_t r[4];
                    ldsm4t(r, Bg + (uint32_t)((ks + 1) * 16 + l15) * SB_B
                                 + (uint32_t)(np * 16 + bhi) * 2);
                    bfr[nxt][np * 2][0] = r[0]; bfr[nxt][np * 2][1] = r[1];
                    bfr[nxt][np * 2 + 1][0] = r[2]; bfr[nxt][np * 2 + 1][1] = r[3];
                }
            }
            #pragma unroll
            for (int mt = 0; mt < 4; mt++)
                #pragma unroll
                for (int nt = 0; nt < 8; nt++)
                    mma16(acc[mt][nt], afr[cur][mt], bfr[cur][nt]);
        }
    }
    __syncthreads();       // mainloop done; smem reused for staging

    // ---- stage gate values through smem (gates live in different warps) ----
    #pragma unroll
    for (int mt = 0; mt < 4; mt++) {
        #pragma unroll
        for (int nt = 0; nt < 8; nt++) {
            int r0 = wm * 64 + mt * 16 + (lane >> 2);
            int cb = g * 64 + nt * 8 + (lane & 3) * 2;
            *(float2*)&sm[(size_t)r0 * SS + cb]       = make_float2(acc[mt][nt][0], acc[mt][nt][1]);
            *(float2*)&sm[(size_t)(r0 + 8) * SS + cb] = make_float2(acc[mt][nt][2], acc[mt][nt][3]);
        }
    }
    __syncthreads();

    // ---- fused LSTM combine + store ----
    const int nl   = tid & 63;
    const int mseg = tid >> 6;            // 0..3
    const int n    = n0 + nl;
    const float Bf = __ldg(bf + n);
    const float Bi = __ldg(bi + n);
    const float Bc = __ldg(bc + n);
    const float Bo = __ldg(bo + n);

    #pragma unroll 4
    for (int r = 0; r < 32; r++) {
        int m = r * 4 + mseg;
        const float* row = &sm[(size_t)m * SS];
        float gf = row[nl]       + Bf;
        float gi = row[64 + nl]  + Bi;
        float gc = row[128 + nl] + Bc;
        float go = row[192 + nl] + Bo;

        float F  = sigf(gf);
        float I  = sigf(gi);
        float O  = sigf(go);
        float CD = tanhf_e(gc);

        size_t gidx = (size_t)(m0 + m) * 1024 + n;
        float cold = __ldg(cellp + gidx);
        float nc = fmaf(F, cold, I * CD);
        float nh = O * tanhf_e(nc);
        outh[gidx] = nh;
        outc[gidx] = nc;
    }
}

extern "C" void kernel_launch(void* const* d_in, const int* in_sizes, int n_in,
                              void* d_out, int out_size)
{
    const float* x    = (const float*)d_in[0];   // [B, 1024]
    const float* h    = (const float*)d_in[1];   // [B, 1024]
    const float* cell = (const float*)d_in[2];   // [B, 1024]
    const float* Wf   = (const float*)d_in[3];   // [2048, 1024]
    const float* bf   = (const float*)d_in[4];
    const float* Wi   = (const float*)d_in[5];
    const float* bi   = (const float*)d_in[6];
    const float* Wc   = (const float*)d_in[7];
    const float* bc   = (const float*)d_in[8];
    const float* Wo   = (const float*)d_in[9];
    const float* bo   = (const float*)d_in[10];

    const int B = in_sizes[0] / 1024;            // 8192

    static bool attr_set = false;
    if (!attr_set) {
        cudaFuncSetAttribute(lstm_mma, cudaFuncAttributeMaxDynamicSharedMemorySize,
                             SMEM_BYTES);
        attr_set = true;
    }

    convert_kernel<<<2048, 256>>>(x, h, Wf, Wi, Wc, Wo);

    float* outh = (float*)d_out;
    float* outc = (float*)d_out + (size_t)B * 1024;

    dim3 grid(B / 128, 16);
    lstm_mma<<<grid, 256, SMEM_BYTES>>>(cell, bf, bi, bc, bo, outh, outc);
}

// round 10
// speedup vs baseline: 2.1509x; 1.5368x over previous
#include <cuda_runtime.h>
#include <cuda_fp16.h>
#include <cstdint>

// ============================================================================
// LSTM cell, two kernels:
//  1) convert: fp32 -> fp16 into __device__ globals (combined [x|h], W per gate)
//  2) GEMM via mma.sync fp16 m16n8k16, cp.async mainloop.
// R9: 2 CTAs/SM (independent barriers cover each other's sync/ldsm bubbles).
// CTA: M=64, per-gate N=64 (4 gates), 8 warps = 2(M) x 4(gate), warp 32x64.
// BK=32, 64 iters, 4 smem stages (94KB/CTA), acc 64 regs (128-reg budget).
// ============================================================================

#define BATCH     8192
#define SA_B      80                          // A smem row stride bytes (32 fp16 + 16 pad)
#define SB_B      144                         // B smem row stride bytes (64 fp16 + 16 pad)
#define A_BYTES   (64 * SA_B)                 // 5120
#define BG_BYTES  (32 * SB_B)                 // 4608 per gate
#define STAGE_BYTES (A_BYTES + 4 * BG_BYTES)  // 23552
#define NSTAGES   4
#define SS        260                         // epilogue staging stride (floats)
#define SMEM_BYTES (NSTAGES * STAGE_BYTES)    // 94208 (> epi 66560)

__device__ static __half A_h[(size_t)BATCH * 2048];      // combined [x|h], 32MB
__device__ static __half W_h[4][(size_t)2048 * 1024];    // per-gate weights, 16MB

// ---------------------------------------------------------------- convert ---
__global__ void __launch_bounds__(256) convert_kernel(
    const float* __restrict__ x, const float* __restrict__ h,
    const float* __restrict__ Wf, const float* __restrict__ Wi,
    const float* __restrict__ Wc, const float* __restrict__ Wo)
{
    const size_t NA = (size_t)BATCH * 2048 / 4;
    const size_t NW = (size_t)2048 * 1024 / 4;
    const size_t total = NA + 4 * NW;
    const size_t stride = (size_t)gridDim.x * blockDim.x;

    for (size_t i = (size_t)blockIdx.x * blockDim.x + threadIdx.x;
         i < total; i += stride) {
        float4 v;
        __half* dst;
        if (i < NA) {
            size_t m = i >> 9;
            size_t k = (i & 511) * 4;
            const float* src = (k < 1024) ? (x + m * 1024 + k)
                                          : (h + m * 1024 + (k - 1024));
            v = *reinterpret_cast<const float4*>(src);
            dst = &A_h[i * 4];
        } else {
            size_t j = i - NA;
            size_t g = j / NW;
            size_t r = j - g * NW;
            const float* Wg = (g == 0) ? Wf : (g == 1) ? Wi : (g == 2) ? Wc : Wo;
            v = *reinterpret_cast<const float4*>(Wg + r * 4);
            dst = &W_h[g][r * 4];
        }
        __half2 lo = __floats2half2_rn(v.x, v.y);
        __half2 hi = __floats2half2_rn(v.z, v.w);
        uint2 out = { *reinterpret_cast<uint32_t*>(&lo), *reinterpret_cast<uint32_t*>(&hi) };
        *reinterpret_cast<uint2*>(dst) = out;
    }
}

// ------------------------------------------------------------------ GEMM ----
__device__ __forceinline__ uint32_t s2u(const void* p) {
    uint32_t a;
    asm("{ .reg .u64 t; cvta.to.shared.u64 t, %1; cvt.u32.u64 %0, t; }"
        : "=r"(a) : "l"(p));
    return a;
}
__device__ __forceinline__ void cp16(uint32_t dst, const __half* src) {
    asm volatile("cp.async.cg.shared.global [%0], [%1], 16;" :: "r"(dst), "l"(src));
}
#define CP_COMMIT() asm volatile("cp.async.commit_group;" ::: "memory")
#define CP_WAIT(n)  asm volatile("cp.async.wait_group %0;" :: "n"(n) : "memory")

__device__ __forceinline__ void ldsm4(uint32_t* r, uint32_t addr) {
    asm volatile("ldmatrix.sync.aligned.m8n8.x4.shared.b16 {%0,%1,%2,%3}, [%4];"
                 : "=r"(r[0]), "=r"(r[1]), "=r"(r[2]), "=r"(r[3]) : "r"(addr));
}
__device__ __forceinline__ void ldsm4t(uint32_t* r, uint32_t addr) {
    asm volatile("ldmatrix.sync.aligned.m8n8.x4.trans.shared.b16 {%0,%1,%2,%3}, [%4];"
                 : "=r"(r[0]), "=r"(r[1]), "=r"(r[2]), "=r"(r[3]) : "r"(addr));
}
__device__ __forceinline__ void mma16(float* d, const uint32_t* a, const uint32_t* b) {
    asm volatile(
        "mma.sync.aligned.m16n8k16.row.col.f32.f16.f16.f32 "
        "{%0,%1,%2,%3}, {%4,%5,%6,%7}, {%8,%9}, {%0,%1,%2,%3};"
        : "+f"(d[0]), "+f"(d[1]), "+f"(d[2]), "+f"(d[3])
        : "r"(a[0]), "r"(a[1]), "r"(a[2]), "r"(a[3]), "r"(b[0]), "r"(b[1]));
}
__device__ __forceinline__ float sigf(float v) {
    return __fdividef(1.0f, 1.0f + __expf(-v));
}
__device__ __forceinline__ float tanhf_e(float v) {
    float ax = fabsf(v);
    float e = __expf(-2.0f * ax);
    float t = __fdividef(1.0f - e, 1.0f + e);
    return copysignf(t, v);
}

// cp.async one BK=32 stage: A 256 chunks (1/thread), B 1024 chunks (4/thread)
__device__ __forceinline__ void load_stage(int T, int tid, uint32_t sb, int m0, int n0)
{
    const uint32_t Ab = sb + (T % NSTAGES) * STAGE_BYTES;
    const int k0 = T * 32;
    {
        int row = tid >> 2, col = tid & 3;
        cp16(Ab + row * SA_B + col * 16,
             &A_h[(size_t)(m0 + row) * 2048 + k0 + col * 8]);
    }
    const uint32_t Bb = Ab + A_BYTES;
    #pragma unroll
    for (int c = 0; c < 4; c++) {          // gate == c
        int kr = tid >> 3, col = tid & 7;
        cp16(Bb + c * BG_BYTES + kr * SB_B + col * 16,
             &W_h[c][(size_t)(k0 + kr) * 1024 + n0 + col * 8]);
    }
}

__global__ void __launch_bounds__(256, 2)
lstm_mma(const float* __restrict__ cellp,
         const float* __restrict__ bf, const float* __restrict__ bi,
         const float* __restrict__ bc, const float* __restrict__ bo,
         float* __restrict__ outh, float* __restrict__ outc)
{
    extern __shared__ float sm[];
    const uint32_t sb = s2u(sm);

    const int tid  = threadIdx.x;
    const int lane = tid & 31;
    const int wid  = tid >> 5;
    const int g    = wid & 3;             // gate handled by this warp
    const int wm   = wid >> 2;            // M half within CTA (0/1) -> 32 rows
    const int m0   = blockIdx.x * 64;
    const int n0   = blockIdx.y * 64;

    const int l15  = lane & 15;
    const int ahi  = (lane >> 4) * 16;    // A: 16B k-half select
    const int bhi  = (lane >> 4) * 8;     // B: n-chunk select

    float acc[2][8][4];
    #pragma unroll
    for (int mt = 0; mt < 2; mt++)
        #pragma unroll
        for (int nt = 0; nt < 8; nt++)
            #pragma unroll
            for (int j = 0; j < 4; j++) acc[mt][nt][j] = 0.0f;

    load_stage(0, tid, sb, m0, n0); CP_COMMIT();
    load_stage(1, tid, sb, m0, n0); CP_COMMIT();

    for (int t = 0; t < 64; t++) {
        if (t < 62) {
            load_stage(t + 2, tid, sb, m0, n0);
            CP_COMMIT();
            CP_WAIT(2);
        } else if (t == 62) {
            CP_WAIT(1);
        } else {
            CP_WAIT(0);
        }
        __syncthreads();

        const uint32_t Ab = sb + (t % NSTAGES) * STAGE_BYTES;
        const uint32_t Bg = Ab + A_BYTES + g * BG_BYTES;

        #pragma unroll
        for (int ks = 0; ks < 2; ks++) {          // two k16 steps (BK=32)
            uint32_t a[2][4];
            #pragma unroll
            for (int mt = 0; mt < 2; mt++)
                ldsm4(a[mt], Ab + (uint32_t)(wm * 32 + mt * 16 + l15) * SA_B
                               + (uint32_t)(ks * 32 + ahi));
            uint32_t b[8][2];
            #pragma unroll
            for (int np = 0; np < 4; np++) {
                uint32_t r[4];
                ldsm4t(r, Bg + (uint32_t)(ks * 16 + l15) * SB_B
                             + (uint32_t)(np * 16 + bhi) * 2);
                b[np * 2][0] = r[0]; b[np * 2][1] = r[1];
                b[np * 2 + 1][0] = r[2]; b[np * 2 + 1][1] = r[3];
            }
            #pragma unroll
            for (int mt = 0; mt < 2; mt++)
                #pragma unroll
                for (int nt = 0; nt < 8; nt++)
                    mma16(acc[mt][nt], a[mt], b[nt]);
        }
    }
    __syncthreads();       // mainloop done; smem reused for staging

    // ---- stage gate values through smem (gates live in different warps) ----
    #pragma unroll
    for (int mt = 0; mt < 2; mt++) {
        #pragma unroll
        for (int nt = 0; nt < 8; nt++) {
            int r0 = wm * 32 + mt * 16 + (lane >> 2);
            int cb = g * 64 + nt * 8 + (lane & 3) * 2;
            *(float2*)&sm[(size_t)r0 * SS + cb]       = make_float2(acc[mt][nt][0], acc[mt][nt][1]);
            *(float2*)&sm[(size_t)(r0 + 8) * SS + cb] = make_float2(acc[mt][nt][2], acc[mt][nt][3]);
        }
    }
    __syncthreads();

    // ---- fused LSTM combine + store (64 x 64 tile, 16 elems/thread) ----
    const int nl   = tid & 63;
    const int mseg = tid >> 6;            // 0..3
    const int n    = n0 + nl;
    const float Bf = __ldg(bf + n);
    const float Bi = __ldg(bi + n);
    const float Bc = __ldg(bc + n);
    const float Bo = __ldg(bo + n);

    #pragma unroll 4
    for (int r = 0; r < 16; r++) {
        int m = r * 4 + mseg;
        const float* row = &sm[(size_t)m * SS];
        float gf = row[nl]       + Bf;
        float gi = row[64 + nl]  + Bi;
        float gc = row[128 + nl] + Bc;
        float go = row[192 + nl] + Bo;

        float F  = sigf(gf);
        float I  = sigf(gi);
        float O  = sigf(go);
        float CD = tanhf_e(gc);

        size_t gidx = (size_t)(m0 + m) * 1024 + n;
        float cold = __ldg(cellp + gidx);
        float nc = fmaf(F, cold, I * CD);
        float nh = O * tanhf_e(nc);
        outh[gidx] = nh;
        outc[gidx] = nc;
    }
}

extern "C" void kernel_launch(void* const* d_in, const int* in_sizes, int n_in,
                              void* d_out, int out_size)
{
    const float* x    = (const float*)d_in[0];   // [B, 1024]
    const float* h    = (const float*)d_in[1];   // [B, 1024]
    const float* cell = (const float*)d_in[2];   // [B, 1024]
    const float* Wf   = (const float*)d_in[3];   // [2048, 1024]
    const float* bf   = (const float*)d_in[4];
    const float* Wi   = (const float*)d_in[5];
    const float* bi   = (const float*)d_in[6];
    const float* Wc   = (const float*)d_in[7];
    const float* bc   = (const float*)d_in[8];
    const float* Wo   = (const float*)d_in[9];
    const float* bo   = (const float*)d_in[10];

    const int B = in_sizes[0] / 1024;            // 8192

    static bool attr_set = false;
    if (!attr_set) {
        cudaFuncSetAttribute(lstm_mma, cudaFuncAttributeMaxDynamicSharedMemorySize,
                             SMEM_BYTES);
        attr_set = true;
    }

    convert_kernel<<<2048, 256>>>(x, h, Wf, Wi, Wc, Wo);

    float* outh = (float*)d_out;
    float* outc = (float*)d_out + (size_t)B * 1024;

    dim3 grid(B / 64, 16);
    lstm_mma<<<grid, 256, SMEM_BYTES>>>(cell, bf, bi, bc, bo, outh, outc);
}